// round 2
// baseline (speedup 1.0000x reference)
#include <cuda_runtime.h>
#include <cuda_bf16.h>
#include <math_constants.h>

// GAT layer, N=4096, F=128, H=8, D=8 (HD=64)
// Inputs (metadata order): X[4096,128], A[4096,4096], W[128,64],
//                          att_self[64], att_neigh[64], bias[64]
// Output: float [4096, 64]

#define N_NODES 4096
#define F_IN    128
#define HD      64
#define H_NUM   8
#define D_SZ    8

// Scratch (no allocation allowed in kernel_launch)
__device__ float g_feats[N_NODES * HD];
__device__ float g_as[N_NODES * H_NUM];
__device__ float g_an[N_NODES * H_NUM];

// ---------------------------------------------------------------------------
// Kernel 1: feats = X @ W  (per-head reshape implicit), plus
//   a_s[i,h] = sum_d feats[i,h,d] * att_self[h,d]
//   a_n[i,h] = sum_d feats[i,h,d] * att_neigh[h,d]
// 16 rows per block, 256 threads. Each thread computes 4 consecutive output
// columns (one float4), which always lie within a single head.
// ---------------------------------------------------------------------------
#define K1_ROWS 16
__global__ __launch_bounds__(256) void proj_kernel(
    const float* __restrict__ X, const float* __restrict__ W,
    const float* __restrict__ att_s, const float* __restrict__ att_n)
{
    __shared__ float Ws[F_IN * HD];        // 32 KB
    __shared__ float Xs[K1_ROWS * 129];    // padded stride to kill bank conflicts
    __shared__ float As[HD], An[HD];

    const int t = threadIdx.x;
    const int rowbase = blockIdx.x * K1_ROWS;

    // Stage W (float4), att vectors, X tile
    for (int idx = t; idx < (F_IN * HD) / 4; idx += 256)
        ((float4*)Ws)[idx] = ((const float4*)W)[idx];
    if (t < HD) { As[t] = att_s[t]; An[t] = att_n[t]; }
    for (int idx = t; idx < K1_ROWS * F_IN; idx += 256) {
        int r = idx >> 7, f = idx & 127;
        Xs[r * 129 + f] = X[(size_t)(rowbase + r) * F_IN + f];
    }
    __syncthreads();

    const int c4 = (t & 15) * 4;   // output column base (0..60, step 4)
    const int rl = t >> 4;         // local row 0..15
    const int r  = rowbase + rl;

    float a0 = 0.f, a1 = 0.f, a2 = 0.f, a3 = 0.f;
#pragma unroll 8
    for (int f = 0; f < F_IN; f++) {
        float4 w = *(const float4*)&Ws[f * HD + c4];
        float  x = Xs[rl * 129 + f];
        a0 = fmaf(x, w.x, a0);
        a1 = fmaf(x, w.y, a1);
        a2 = fmaf(x, w.z, a2);
        a3 = fmaf(x, w.w, a3);
    }
    *(float4*)&g_feats[r * HD + c4] = make_float4(a0, a1, a2, a3);

    // Partial attention scores over this thread's 4 d-columns (same head)
    float asum = a0 * As[c4] + a1 * As[c4 + 1] + a2 * As[c4 + 2] + a3 * As[c4 + 3];
    float ansm = a0 * An[c4] + a1 * An[c4 + 1] + a2 * An[c4 + 2] + a3 * An[c4 + 3];
    // Partner thread (t^1) holds the other half of the same head, same row
    asum += __shfl_xor_sync(0xffffffffu, asum, 1);
    ansm += __shfl_xor_sync(0xffffffffu, ansm, 1);
    if ((t & 1) == 0) {
        int h = (t & 15) >> 1;
        g_as[r * H_NUM + h] = asum;
        g_an[r * H_NUM + h] = ansm;
    }
}

// ---------------------------------------------------------------------------
// Kernel 2: one block per row i.
// Phase 1: 128 threads scan the full A row (float4), compact nonzero column
//          indices into shared memory (worst case 4096 entries -> 16 KB).
// Phase 2: 64 threads, thread t owns (h,d) = (t/8, t%8). Online softmax over
//          the nonzero neighbor list; masked entries contribute exactly 0 in
//          the reference (exp underflow), so skipping them is exact.
// ---------------------------------------------------------------------------
__global__ __launch_bounds__(128) void gat_kernel(
    const float* __restrict__ A, const float* __restrict__ bias,
    float* __restrict__ out)
{
    __shared__ int nz[N_NODES];   // 16 KB — cannot overflow
    __shared__ int cnt;

    const int i = blockIdx.x;
    const int t = threadIdx.x;
    if (t == 0) cnt = 0;
    __syncthreads();

    const float4* Arow = (const float4*)(A + (size_t)i * N_NODES);
#pragma unroll 2
    for (int c = t; c < N_NODES / 4; c += 128) {
        float4 v = Arow[c];
        int j = c * 4;
        if (v.x != 0.f) nz[atomicAdd(&cnt, 1)] = j;
        if (v.y != 0.f) nz[atomicAdd(&cnt, 1)] = j + 1;
        if (v.z != 0.f) nz[atomicAdd(&cnt, 1)] = j + 2;
        if (v.w != 0.f) nz[atomicAdd(&cnt, 1)] = j + 3;
    }
    __syncthreads();

    if (t >= HD) return;
    const int n = cnt;
    const int h = t >> 3;

    const float asi = g_as[i * H_NUM + h];
    float m = -CUDART_INF_F, s = 0.f, acc = 0.f;
    for (int k = 0; k < n; k++) {
        int j = nz[k];
        float l = asi + g_an[j * H_NUM + h];
        l = l > 0.f ? l : 0.2f * l;          // leaky_relu(0.2)
        float mn = fmaxf(m, l);
        float sc = __expf(m - mn);           // exp(-inf)=0 on first iter
        float w  = __expf(l - mn);
        s   = s * sc + w;
        acc = acc * sc + w * g_feats[j * HD + t];
        m = mn;
    }
    float o = acc / s + bias[t];
    out[(size_t)i * HD + t] = fmaxf(o, 0.f);
}

// ---------------------------------------------------------------------------
extern "C" void kernel_launch(void* const* d_in, const int* in_sizes, int n_in,
                              void* d_out, int out_size)
{
    const float* X      = (const float*)d_in[0];
    const float* A      = (const float*)d_in[1];
    const float* W      = (const float*)d_in[2];
    const float* att_s  = (const float*)d_in[3];
    const float* att_n  = (const float*)d_in[4];
    const float* bias   = (const float*)d_in[5];
    float* out = (float*)d_out;

    proj_kernel<<<N_NODES / K1_ROWS, 256>>>(X, W, att_s, att_n);
    gat_kernel<<<N_NODES, 128>>>(A, bias, out);
}

// round 3
// speedup vs baseline: 1.0531x; 1.0531x over previous
#include <cuda_runtime.h>
#include <cuda_bf16.h>
#include <math_constants.h>

// GAT layer, N=4096, F=128, H=8, D=8 (HD=64)
// Inputs: X[4096,128], A[4096,4096], W[128,64], att_self[64], att_neigh[64], bias[64]
// Output: float [4096, 64]

#define N_NODES 4096
#define F_IN    128
#define HD      64
#define H_NUM   8

__device__ float g_feats[N_NODES * HD];
__device__ float g_as[N_NODES * H_NUM];
__device__ float g_an[N_NODES * H_NUM];

// ---------------------------------------------------------------------------
// Kernel 1: feats = X @ W, plus per-head scores a_s, a_n.
// 16 rows per block, 128 threads, each thread computes 2 rows x 4 cols
// (rows rl and rl+8 share every W float4 load -> half the LDS traffic).
// ---------------------------------------------------------------------------
#define K1_ROWS 16
__global__ __launch_bounds__(128) void proj_kernel(
    const float* __restrict__ X, const float* __restrict__ W,
    const float* __restrict__ att_s, const float* __restrict__ att_n)
{
    __shared__ float Ws[F_IN * HD];          // 32 KB
    __shared__ float Xs[K1_ROWS * F_IN];     // 8 KB

    const int t = threadIdx.x;
    const int rowbase = blockIdx.x * K1_ROWS;

    for (int idx = t; idx < (F_IN * HD) / 4; idx += 128)
        ((float4*)Ws)[idx] = ((const float4*)W)[idx];
    for (int idx = t; idx < K1_ROWS * F_IN / 4; idx += 128)
        ((float4*)Xs)[idx] = ((const float4*)(X + (size_t)rowbase * F_IN))[idx];
    __syncthreads();

    const int c4 = (t & 15) * 4;     // output column base (within one head)
    const int rl = t >> 4;           // local row 0..7; also handles rl+8

    float4 as4 = *(const float4*)&att_s[c4];
    float4 an4 = *(const float4*)&att_n[c4];

    float a0 = 0.f, a1 = 0.f, a2 = 0.f, a3 = 0.f;
    float b0 = 0.f, b1 = 0.f, b2 = 0.f, b3 = 0.f;
#pragma unroll 8
    for (int f = 0; f < F_IN; f++) {
        float4 w = *(const float4*)&Ws[f * HD + c4];
        float x0 = Xs[rl * F_IN + f];
        float x1 = Xs[(rl + 8) * F_IN + f];
        a0 = fmaf(x0, w.x, a0); a1 = fmaf(x0, w.y, a1);
        a2 = fmaf(x0, w.z, a2); a3 = fmaf(x0, w.w, a3);
        b0 = fmaf(x1, w.x, b0); b1 = fmaf(x1, w.y, b1);
        b2 = fmaf(x1, w.z, b2); b3 = fmaf(x1, w.w, b3);
    }
    const int r0 = rowbase + rl, r1 = rowbase + rl + 8;
    *(float4*)&g_feats[r0 * HD + c4] = make_float4(a0, a1, a2, a3);
    *(float4*)&g_feats[r1 * HD + c4] = make_float4(b0, b1, b2, b3);

    // Per-head scores; partner t^1 holds the other 4 d-columns of the head.
    float as0 = a0 * as4.x + a1 * as4.y + a2 * as4.z + a3 * as4.w;
    float an0 = a0 * an4.x + a1 * an4.y + a2 * an4.z + a3 * an4.w;
    float as1 = b0 * as4.x + b1 * as4.y + b2 * as4.z + b3 * as4.w;
    float an1 = b0 * an4.x + b1 * an4.y + b2 * an4.z + b3 * an4.w;
    as0 += __shfl_xor_sync(0xffffffffu, as0, 1);
    an0 += __shfl_xor_sync(0xffffffffu, an0, 1);
    as1 += __shfl_xor_sync(0xffffffffu, as1, 1);
    an1 += __shfl_xor_sync(0xffffffffu, an1, 1);
    if ((t & 1) == 0) {
        int h = (t & 15) >> 1;
        g_as[r0 * H_NUM + h] = as0;  g_an[r0 * H_NUM + h] = an0;
        g_as[r1 * H_NUM + h] = as1;  g_an[r1 * H_NUM + h] = an1;
    }
}

// ---------------------------------------------------------------------------
// Kernel 2: one block (256 threads) per row i.
//  Phase 1: front-batched float4 scan of the A row, compact nz indices.
//  Phase 2a: warp h computes softmax max M[h] and sum S[h] lane-parallel.
//  Phase 2b: all 256 threads do the weighted aggregation (4 k-groups),
//            smem-reduce, write relu(acc/S + bias).
// Masked entries contribute exactly 0 in the reference (fp32 exp underflow),
// so the sparse sum is exact.
// ---------------------------------------------------------------------------
__global__ __launch_bounds__(256) void gat_kernel(
    const float* __restrict__ A, const float* __restrict__ bias,
    float* __restrict__ out)
{
    __shared__ int   nz[N_NODES];     // 16 KB, worst case safe
    __shared__ int   cnt;
    __shared__ float Msh[H_NUM], Ssh[H_NUM];
    __shared__ float accbuf[256];

    const int i = blockIdx.x;
    const int t = threadIdx.x;
    if (t == 0) cnt = 0;
    __syncthreads();

    // ---- Phase 1: scan (front-batched loads, MLP=4 per thread) ----
    const float4* Arow = (const float4*)(A + (size_t)i * N_NODES);
    float4 v[4];
#pragma unroll
    for (int q = 0; q < 4; q++) v[q] = Arow[t + 256 * q];
#pragma unroll
    for (int q = 0; q < 4; q++) {
        int j = (t + 256 * q) * 4;
        if (v[q].x != 0.f) nz[atomicAdd(&cnt, 1)] = j;
        if (v[q].y != 0.f) nz[atomicAdd(&cnt, 1)] = j + 1;
        if (v[q].z != 0.f) nz[atomicAdd(&cnt, 1)] = j + 2;
        if (v[q].w != 0.f) nz[atomicAdd(&cnt, 1)] = j + 3;
    }
    __syncthreads();
    const int n = cnt;

    // ---- Phase 2a: per-head softmax stats, warp h owns head h ----
    const int wid = t >> 5, lane = t & 31;
    {
        const int h = wid;
        const float asi = g_as[i * H_NUM + h];
        float m = -1e30f, s = 0.f;
        for (int k = lane; k < n; k += 32) {
            int j = nz[k];
            float l = asi + g_an[j * H_NUM + h];
            l = l > 0.f ? l : 0.2f * l;                // leaky_relu(0.2)
            float mn = fmaxf(m, l);
            s = s * __expf(m - mn) + __expf(l - mn);
            m = mn;
        }
#pragma unroll
        for (int o = 16; o > 0; o >>= 1) {
            float m2 = __shfl_xor_sync(0xffffffffu, m, o);
            float s2 = __shfl_xor_sync(0xffffffffu, s, o);
            float mn = fmaxf(m, m2);
            s = s * __expf(m - mn) + s2 * __expf(m2 - mn);
            m = mn;
        }
        if (lane == 0) { Msh[h] = m; Ssh[h] = s; }
    }
    __syncthreads();

    // ---- Phase 2b: parallel weighted aggregation ----
    const int o   = t & 63;          // output element (h*8+d)
    const int grp = t >> 6;          // 0..3: k-strided group
    const int h   = o >> 3;
    const float asi = g_as[i * H_NUM + h];
    const float M   = Msh[h];

    float acc = 0.f;
#pragma unroll 4
    for (int k = grp; k < n; k += 4) {
        int j = nz[k];
        float l = asi + g_an[j * H_NUM + h];
        l = l > 0.f ? l : 0.2f * l;
        float w = __expf(l - M);
        acc = fmaf(w, g_feats[j * HD + o], acc);
    }
    accbuf[t] = acc;
    __syncthreads();

    if (t < HD) {
        float a = accbuf[t] + accbuf[t + 64] + accbuf[t + 128] + accbuf[t + 192];
        float r = a / Ssh[h] + bias[t];
        out[(size_t)i * HD + t] = fmaxf(r, 0.f);
    }
}

// ---------------------------------------------------------------------------
extern "C" void kernel_launch(void* const* d_in, const int* in_sizes, int n_in,
                              void* d_out, int out_size)
{
    const float* X     = (const float*)d_in[0];
    const float* A     = (const float*)d_in[1];
    const float* W     = (const float*)d_in[2];
    const float* att_s = (const float*)d_in[3];
    const float* att_n = (const float*)d_in[4];
    const float* bias  = (const float*)d_in[5];
    float* out = (float*)d_out;

    proj_kernel<<<N_NODES / K1_ROWS, 128>>>(X, W, att_s, att_n);
    gat_kernel<<<N_NODES, 256>>>(A, bias, out);
}